// round 12
// baseline (speedup 1.0000x reference)
#include <cuda_runtime.h>
#include <cuda_bf16.h>
#include <math.h>
#include <stdint.h>

#define BATCH 32768
#define B2    (2 * BATCH)
#define NL 2

// ---------------- scratch (device globals; no allocation) ----------------
__device__ float g_x [(size_t)B2 * 256];
__device__ float g_xn[(size_t)B2 * 256];
__device__ float g_h [(size_t)B2 * 512];
__device__ float g_g [(size_t)B2 * 512];
__device__ float g_y [(size_t)B2 * 512];

// packed weights: bf16 hi/lo, layout [S][R][64] rows pre-swizzled (chunk ^= row&7)
__device__ __nv_bfloat16 g_w_hi[1 << 20];
__device__ __nv_bfloat16 g_w_lo[1 << 20];
#define WOFF_MW   0
#define WOFF_RW   131072
#define WOFF_INW  147456
#define WOFF_OUTW (147456 + 2*262144)

__device__ __forceinline__ float silu_f(float x) { return x / (1.0f + __expf(-x)); }
__device__ __forceinline__ float softplus_f(float x) { return (x > 20.0f) ? x : log1pf(__expf(x)); }

__device__ __forceinline__ uint32_t smem_u32_of(const void* p) {
    uint32_t a;
    asm("{ .reg .u64 t; cvta.to.shared.u64 t, %1; cvt.u32.u64 %0, t; }" : "=r"(a) : "l"(p));
    return a;
}
__device__ __forceinline__ uint32_t swzb(uint32_t b) { return b ^ ((b >> 3) & 0x70); }

__device__ __forceinline__ void bsplit2(float x0, float x1, uint32_t& hi, uint32_t& lo) {
    __nv_bfloat16 h0 = __float2bfloat16_rn(x0), h1 = __float2bfloat16_rn(x1);
    float r0 = x0 - __bfloat162float(h0), r1 = x1 - __bfloat162float(h1);
    __nv_bfloat16 l0 = __float2bfloat16_rn(r0), l1 = __float2bfloat16_rn(r1);
    hi = ((uint32_t)__bfloat16_as_ushort(h1) << 16) | __bfloat16_as_ushort(h0);
    lo = ((uint32_t)__bfloat16_as_ushort(l1) << 16) | __bfloat16_as_ushort(l0);
}

#define STS128U(addr, a, b, c, d) \
    asm volatile("st.shared.v4.b32 [%0], {%1, %2, %3, %4};" \
                 :: "r"(addr), "r"(a), "r"(b), "r"(c), "r"(d) : "memory")

#define LDSM4(r0, r1, r2, r3, a) \
    asm volatile("ldmatrix.sync.aligned.m8n8.x4.shared.b16 {%0,%1,%2,%3}, [%4];" \
                 : "=r"(r0), "=r"(r1), "=r"(r2), "=r"(r3) : "r"(a))

__device__ __forceinline__ void mma_bf16(float* c, const uint32_t* a, const uint32_t* b) {
    asm volatile("mma.sync.aligned.m16n8k16.row.col.f32.bf16.bf16.f32 "
                 "{%0,%1,%2,%3}, {%4,%5,%6,%7}, {%8,%9}, {%0,%1,%2,%3};"
                 : "+f"(c[0]), "+f"(c[1]), "+f"(c[2]), "+f"(c[3])
                 : "r"(a[0]), "r"(a[1]), "r"(a[2]), "r"(a[3]), "r"(b[0]), "r"(b[1]));
}

__device__ __forceinline__ void cp16(uint32_t d, const void* s) {
    asm volatile("cp.async.cg.shared.global [%0], [%1], 16;" :: "r"(d), "l"(s) : "memory");
}
#define CP_COMMIT() asm volatile("cp.async.commit_group;" ::: "memory")
#define CP_WAIT0()  asm volatile("cp.async.wait_group 0;" ::: "memory")

// ---------------- pack weights: fp32 [R,K] -> swizzled bf16 hi/lo [S][R][64] ----------------
__device__ __forceinline__ void pack_one(int id, const float* src, __nv_bfloat16* hi,
                                         __nv_bfloat16* lo, int R, int K)
{
    int c8  = id & 7;
    int rs  = id >> 3;
    int row = rs % R;
    int s   = rs / R;
    int k0  = s * 64 + c8 * 8;
    const float* sp = src + (size_t)row * K;
    uint32_t h[4], l[4];
    #pragma unroll
    for (int p = 0; p < 4; p++) {
        int k = k0 + p * 2;
        float x0 = (k     < K) ? sp[k]     : 0.0f;
        float x1 = (k + 1 < K) ? sp[k + 1] : 0.0f;
        bsplit2(x0, x1, h[p], l[p]);
    }
    size_t off = ((size_t)s * R + row) * 64 + (size_t)(c8 ^ (row & 7)) * 8;
    *(uint4*)(hi + off) = make_uint4(h[0], h[1], h[2], h[3]);
    *(uint4*)(lo + off) = make_uint4(l[0], l[1], l[2], l[3]);
}

__global__ __launch_bounds__(256)
void pack_kernel(const float* __restrict__ src, __nv_bfloat16* __restrict__ hi,
                 __nv_bfloat16* __restrict__ lo, int R, int K, int S)
{
    int id = blockIdx.x * 256 + threadIdx.x;
    if (id >= R * S * 8) return;
    pack_one(id, src, hi, lo, R, K);
}

// methyl_w (256x500, S=8) + rna_w (256x47, S=1) in one launch
__global__ __launch_bounds__(256)
void pack2_kernel(const float* __restrict__ mw, const float* __restrict__ rw,
                  __nv_bfloat16* __restrict__ hi, __nv_bfloat16* __restrict__ lo)
{
    int id = blockIdx.x * 256 + threadIdx.x;
    const int n_m = 256 * 8 * 8;          // 16384
    if (id < n_m)
        pack_one(id, mw, hi + WOFF_MW, lo + WOFF_MW, 256, 500);
    else if (id < n_m + 256 * 1 * 8)
        pack_one(id - n_m, rw, hi + WOFF_RW, lo + WOFF_RW, 256, 47);
}

// ---------------- tensor-core GEMM: CTA tile 64x256, 16 warps 2(M)x8(N), warp 32x32 ----------------
// C[M,N] = A[M,K] @ W[N,K]^T via hh+hl+lh bf16 split. BK=64, double-buffered.
// MODE 0: out0 = acc + e0[n]
// MODE 1: n<512: silu(acc*e0[n*4+3]+e1[n]) -> out0 ; else raw -> out1[m*512+(n-512)]
// MODE 2: out0 = acc + e0[m*N+n]
#define A_TILE_B  (64 * 128)               // 8KB
#define W_TILE_B  (256 * 128)              // 32KB
#define STAGE_B   (2 * A_TILE_B + 2 * W_TILE_B)   // 80KB
#define OFF_AH    0
#define OFF_AL    A_TILE_B
#define OFF_WH    (2 * A_TILE_B)
#define OFF_WL    (2 * A_TILE_B + W_TILE_B)
#define GEMM_SMEM (2 * STAGE_B)            // 160KB

template<int MODE>
__global__ __launch_bounds__(512, 1)
void gemm_tc(const float* __restrict__ A, int K,
             const __nv_bfloat16* __restrict__ Whi, const __nv_bfloat16* __restrict__ Wlo, int RW,
             float* __restrict__ out0, float* __restrict__ out1,
             const float* __restrict__ e0, const float* __restrict__ e1,
             int N, int S)
{
    extern __shared__ char smem[];
    const uint32_t sb = smem_u32_of(smem);

    const int tid  = threadIdx.x;
    const int lane = tid & 31;
    const int wid  = tid >> 5;
    const int bm = blockIdx.y * 64;
    const int bn = blockIdx.x * 256;
    const int wm = (wid >> 3) * 32;     // 0 or 32
    const int wn = (wid & 7) * 32;      // 0..224
    const bool k4 = ((K & 3) == 0);

    float acc[2][4][4];
    #pragma unroll
    for (int i = 0; i < 2; i++)
        #pragma unroll
        for (int j = 0; j < 4; j++)
            #pragma unroll
            for (int c = 0; c < 4; c++) acc[i][j][c] = 0.0f;

    float va[8];
    const int am  = tid >> 3;           // 0..63
    const int ac8 = tid & 7;

    auto load_regsA = [&](int s) {
        const int k = s * 64 + ac8 * 8;
        const float* ap = A + (size_t)(bm + am) * K;
        if (k4) {
            #pragma unroll
            for (int h = 0; h < 2; h++) {
                int kk = k + h * 4;
                float4 u = make_float4(0.f, 0.f, 0.f, 0.f);
                if (kk + 4 <= K) u = *(const float4*)(ap + kk);
                va[h*4+0] = u.x; va[h*4+1] = u.y; va[h*4+2] = u.z; va[h*4+3] = u.w;
            }
        } else {
            #pragma unroll
            for (int e = 0; e < 8; e++) {
                int kk = k + e;
                va[e] = (kk < K) ? ap[kk] : 0.0f;
            }
        }
    };
    auto storeA = [&](int st) {
        const uint32_t base = sb + st * STAGE_B;
        uint32_t off = swzb((uint32_t)(am * 128 + ac8 * 16));
        uint32_t h[4], l[4];
        #pragma unroll
        for (int p = 0; p < 4; p++)
            bsplit2(va[2*p], va[2*p+1], h[p], l[p]);
        STS128U(base + OFF_AH + off, h[0], h[1], h[2], h[3]);
        STS128U(base + OFF_AL + off, l[0], l[1], l[2], l[3]);
    };
    auto issueW = [&](int s, int st) {
        const uint32_t base = sb + st * STAGE_B;
        const int row = tid >> 1;       // 0..255
        const int hf  = tid & 1;        // 64B half
        const char* sh = (const char*)(Whi + ((size_t)s * RW + bn + row) * 64) + hf * 64;
        const char* sl = (const char*)(Wlo + ((size_t)s * RW + bn + row) * 64) + hf * 64;
        uint32_t doff = (uint32_t)(row * 128 + hf * 64);
        #pragma unroll
        for (int u = 0; u < 4; u++) {
            cp16(base + OFF_WH + doff + u * 16, sh + u * 16);
            cp16(base + OFF_WL + doff + u * 16, sl + u * 16);
        }
    };

    const int q = lane >> 3;
    const int r = lane & 7;
    auto mma_stage = [&](int st) {
        const uint32_t base = sb + st * STAGE_B;
        const uint32_t Ah = base + OFF_AH, Al = base + OFF_AL;
        const uint32_t Wh = base + OFF_WH, Wl = base + OFF_WL;
        #pragma unroll
        for (int kb = 0; kb < 4; kb++) {
            uint32_t ah[2][4], al[2][4];
            #pragma unroll
            for (int i = 0; i < 2; i++) {
                uint32_t off = swzb((uint32_t)((wm + 16*i + (q & 1) * 8 + r) * 128
                                               + kb * 32 + (q >> 1) * 16));
                LDSM4(ah[i][0], ah[i][1], ah[i][2], ah[i][3], Ah + off);
                LDSM4(al[i][0], al[i][1], al[i][2], al[i][3], Al + off);
            }
            #pragma unroll
            for (int np = 0; np < 2; np++) {
                uint32_t offb = swzb((uint32_t)((wn + 16*np + (q >> 1) * 8 + r) * 128
                                                + kb * 32 + (q & 1) * 16));
                uint32_t bh[4], bl[4];
                LDSM4(bh[0], bh[1], bh[2], bh[3], Wh + offb);
                LDSM4(bl[0], bl[1], bl[2], bl[3], Wl + offb);
                #pragma unroll
                for (int jj = 0; jj < 2; jj++) {
                    int j = np * 2 + jj;
                    uint32_t Bh[2] = {bh[2*jj], bh[2*jj+1]};
                    uint32_t Bl[2] = {bl[2*jj], bl[2*jj+1]};
                    #pragma unroll
                    for (int i = 0; i < 2; i++) {
                        mma_bf16(acc[i][j], ah[i], Bh);
                        mma_bf16(acc[i][j], ah[i], Bl);
                        mma_bf16(acc[i][j], al[i], Bh);
                    }
                }
            }
        }
    };

    issueW(0, 0); CP_COMMIT();
    load_regsA(0);
    storeA(0);
    CP_WAIT0();
    __syncthreads();

    int st = 0;
    for (int s = 0; s < S; s++) {
        const bool more = (s + 1 < S);
        if (more) {
            issueW(s + 1, st ^ 1); CP_COMMIT();
            load_regsA(s + 1);
        }
        mma_stage(st);
        if (more) {
            storeA(st ^ 1);
            CP_WAIT0();
            __syncthreads();
            st ^= 1;
        }
    }

    #pragma unroll
    for (int i = 0; i < 2; i++) {
        int r0 = bm + wm + 16 * i + (lane >> 2);
        #pragma unroll
        for (int j = 0; j < 4; j++) {
            int c = bn + wn + 8 * j + (lane & 3) * 2;
            #pragma unroll
            for (int hrow = 0; hrow < 2; hrow++) {
                int m = r0 + hrow * 8;
                float v0 = acc[i][j][hrow * 2 + 0];
                float v1 = acc[i][j][hrow * 2 + 1];
                if (MODE == 0) {
                    *(float2*)(out0 + (size_t)m * N + c) = make_float2(v0 + e0[c], v1 + e0[c + 1]);
                } else if (MODE == 1) {
                    if (c < 512) {
                        float2 o;
                        o.x = silu_f(fmaf(v0, e0[c * 4 + 3], e1[c]));
                        o.y = silu_f(fmaf(v1, e0[(c + 1) * 4 + 3], e1[c + 1]));
                        *(float2*)(out0 + (size_t)m * 512 + c) = o;
                    } else {
                        *(float2*)(out1 + (size_t)m * 512 + (c - 512)) = make_float2(v0, v1);
                    }
                } else {
                    float2 rr = *(const float2*)(e0 + (size_t)m * N + c);
                    *(float2*)(out0 + (size_t)m * N + c) = make_float2(v0 + rr.x, v1 + rr.y);
                }
            }
        }
    }
}

// ---------------- rmsnorm ----------------
__global__ __launch_bounds__(256)
void rmsnorm_kernel(const float* __restrict__ x, const float* __restrict__ w,
                    float* __restrict__ out)
{
    const int warp = threadIdx.x >> 5;
    const int lane = threadIdx.x & 31;
    const size_t row = (size_t)blockIdx.x * 8 + warp;

    float v[8];
    float ss = 0.0f;
    #pragma unroll
    for (int qq = 0; qq < 8; qq++) {
        v[qq] = x[row * 256 + lane + 32 * qq];
        ss = fmaf(v[qq], v[qq], ss);
    }
    #pragma unroll
    for (int o = 16; o > 0; o >>= 1) ss += __shfl_xor_sync(0xffffffffu, ss, o);
    float inv = rsqrtf(ss * (1.0f / 256.0f) + 1e-5f);
    #pragma unroll
    for (int qq = 0; qq < 8; qq++)
        out[row * 256 + lane + 32 * qq] = v[qq] * inv * w[lane + 32 * qq];
}

// ---------------- fused SSM with smem-staged xp_w ----------------
__global__ __launch_bounds__(512)
void ssm_kernel(const float* __restrict__ h, const float* __restrict__ gate,
                const float* __restrict__ xp_w, const float* __restrict__ dt_w,
                const float* __restrict__ dt_b, const float* __restrict__ Dv,
                float* __restrict__ y)
{
    extern __shared__ float s_xp[];
    #pragma unroll 4
    for (int i = threadIdx.x; i < 48 * 512; i += 512) s_xp[i] = xp_w[i];
    __syncthreads();

    const int warp = threadIdx.x >> 5;
    const int lane = threadIdx.x & 31;
    const size_t row = (size_t)blockIdx.x * 16 + warp;

    const float* hr = h + row * 512;
    float hreg[16];
    #pragma unroll
    for (int qq = 0; qq < 16; qq++) hreg[qq] = hr[lane + 32 * qq];

    float dtv[16], bnv[16];
    float bc = 0.0f;
    #pragma unroll
    for (int j = 0; j < 48; j++) {
        const float* w = s_xp + j * 512;
        float p = 0.0f;
        #pragma unroll
        for (int qq = 0; qq < 16; qq++) p = fmaf(hreg[qq], w[lane + 32 * qq], p);
        #pragma unroll
        for (int o = 16; o > 0; o >>= 1) p += __shfl_xor_sync(0xffffffffu, p, o);
        if (j < 16)       dtv[j] = p;
        else if (j < 32)  bnv[j - 16] = p;
        else              bc = fmaf(bnv[j - 32], p, bc);
    }

    #pragma unroll
    for (int qq = 0; qq < 16; qq++) {
        int i = lane + 32 * qq;
        const float4* wr = (const float4*)(dt_w + (size_t)i * 16);
        float t = dt_b[i];
        #pragma unroll
        for (int c = 0; c < 4; c++) {
            float4 w4 = wr[c];
            t = fmaf(dtv[c * 4 + 0], w4.x, t);
            t = fmaf(dtv[c * 4 + 1], w4.y, t);
            t = fmaf(dtv[c * 4 + 2], w4.z, t);
            t = fmaf(dtv[c * 4 + 3], w4.w, t);
        }
        float sp = softplus_f(t);
        float gv = gate[row * 512 + i];
        y[row * 512 + i] = hreg[qq] * fmaf(sp, bc, Dv[i]) * silu_f(gv);
    }
}

// ---------------- classifier with fused final rmsnorm ----------------
__global__ __launch_bounds__(256)
void cls_kernel(const float* __restrict__ x, const float* __restrict__ wf,
                const float* __restrict__ cw, const float* __restrict__ cb,
                float* __restrict__ out)
{
    const int warp = threadIdx.x >> 5;
    const int lane = threadIdx.x & 31;
    const size_t row = (size_t)blockIdx.x * 8 + warp;

    float va[8], vb[8];
    float sa = 0.0f, sb2 = 0.0f;
    #pragma unroll
    for (int qq = 0; qq < 8; qq++) {
        size_t ia = row * 256 + lane + 32 * qq;
        size_t ib = ((size_t)BATCH + row) * 256 + lane + 32 * qq;
        va[qq] = x[ia]; vb[qq] = x[ib];
        sa  = fmaf(va[qq], va[qq], sa);
        sb2 = fmaf(vb[qq], vb[qq], sb2);
    }
    #pragma unroll
    for (int o = 16; o > 0; o >>= 1) {
        sa  += __shfl_xor_sync(0xffffffffu, sa,  o);
        sb2 += __shfl_xor_sync(0xffffffffu, sb2, o);
    }
    float inva = rsqrtf(sa  * (1.0f / 256.0f) + 1e-5f);
    float invb = rsqrtf(sb2 * (1.0f / 256.0f) + 1e-5f);

    float p[8];
    #pragma unroll
    for (int qq = 0; qq < 8; qq++) {
        float w = wf[lane + 32 * qq];
        p[qq] = 0.5f * (va[qq] * inva + vb[qq] * invb) * w;
    }
    #pragma unroll
    for (int j = 0; j < 5; j++) {
        float s = 0.0f;
        #pragma unroll
        for (int qq = 0; qq < 8; qq++) s = fmaf(p[qq], cw[j * 256 + lane + 32 * qq], s);
        #pragma unroll
        for (int o = 16; o > 0; o >>= 1) s += __shfl_xor_sync(0xffffffffu, s, o);
        if (lane == 0) out[row * 5 + j] = s + cb[j];
    }
}

// ---------------- launch ----------------
extern "C" void kernel_launch(void* const* d_in, const int* in_sizes, int n_in,
                              void* d_out, int out_size)
{
    const float* methyl   = (const float*)d_in[0];
    const float* rna      = (const float*)d_in[1];
    const float* methyl_w = (const float*)d_in[2];
    const float* methyl_b = (const float*)d_in[3];
    const float* rna_w    = (const float*)d_in[4];
    const float* rna_b    = (const float*)d_in[5];
    const float* in_w     = (const float*)d_in[6];
    const float* conv_w   = (const float*)d_in[7];
    const float* conv_b   = (const float*)d_in[8];
    const float* xp_w     = (const float*)d_in[9];
    const float* dt_w     = (const float*)d_in[10];
    const float* dt_b     = (const float*)d_in[11];
    const float* Dv       = (const float*)d_in[13];
    const float* out_w    = (const float*)d_in[14];
    const float* norm_w   = (const float*)d_in[15];
    const float* norm_f_w = (const float*)d_in[16];
    const float* cls_w    = (const float*)d_in[17];
    const float* cls_b    = (const float*)d_in[18];
    float* out = (float*)d_out;

    float* x_p;  cudaGetSymbolAddress((void**)&x_p,  g_x);
    float* xn_p; cudaGetSymbolAddress((void**)&xn_p, g_xn);
    float* h_p;  cudaGetSymbolAddress((void**)&h_p,  g_h);
    float* gg_p; cudaGetSymbolAddress((void**)&gg_p, g_g);
    float* y_p;  cudaGetSymbolAddress((void**)&y_p,  g_y);
    __nv_bfloat16 *w_h, *w_l;
    cudaGetSymbolAddress((void**)&w_h, g_w_hi);
    cudaGetSymbolAddress((void**)&w_l, g_w_lo);

    cudaFuncSetAttribute(ssm_kernel, cudaFuncAttributeMaxDynamicSharedMemorySize, 48 * 512 * sizeof(float));
    cudaFuncSetAttribute(gemm_tc<0>, cudaFuncAttributeMaxDynamicSharedMemorySize, GEMM_SMEM);
    cudaFuncSetAttribute(gemm_tc<1>, cudaFuncAttributeMaxDynamicSharedMemorySize, GEMM_SMEM);
    cudaFuncSetAttribute(gemm_tc<2>, cudaFuncAttributeMaxDynamicSharedMemorySize, GEMM_SMEM);

    dim3 blk(256);
    dim3 gblk(512);

    // launch 0: methyl_w + rna_w packs (combined so launch index 5 is gemm<1>)
    pack2_kernel<<<(256*8*8 + 256*8 + 255) / 256, blk>>>(methyl_w, rna_w, w_h, w_l);
    // launch 1: in_w[0]
    pack_kernel<<<(1024*4*8 + 255) / 256, blk>>>(in_w, w_h + WOFF_INW, w_l + WOFF_INW, 1024, 256, 4);

    // launches 2,3: embeddings (N=256 -> grid.x = 1)
    dim3 grid_emb(1, BATCH / 64);
    gemm_tc<0><<<grid_emb, gblk, GEMM_SMEM>>>(methyl, 500, w_h + WOFF_MW, w_l + WOFF_MW, 256,
                                              x_p, nullptr, methyl_b, nullptr, 256, 8);
    gemm_tc<0><<<grid_emb, gblk, GEMM_SMEM>>>(rna, 47, w_h + WOFF_RW, w_l + WOFF_RW, 256,
                                              x_p + (size_t)BATCH * 256, nullptr, rna_b, nullptr, 256, 1);

    dim3 grid_proj(4, B2 / 64);
    dim3 grid_out(1, B2 / 64);
    dim3 grid_row(B2 / 8);
    dim3 grid_ssm(B2 / 16);
    dim3 grid_cls(BATCH / 8);

    // launch 4: rmsnorm l=0 ; launch 5: gemm<1> l=0  <-- ncu capture target
    rmsnorm_kernel<<<grid_row, blk>>>(x_p, norm_w, xn_p);
    gemm_tc<1><<<grid_proj, gblk, GEMM_SMEM>>>(xn_p, 256,
                                               w_h + WOFF_INW, w_l + WOFF_INW, 1024,
                                               h_p, gg_p, conv_w, conv_b, 1024, 4);
    // deferred packs (before their consumers)
    pack_kernel<<<(256*8*8 + 255) / 256, blk>>>(out_w, w_h + WOFF_OUTW, w_l + WOFF_OUTW, 256, 512, 8);
    pack_kernel<<<(1024*4*8 + 255) / 256, blk>>>(in_w + (size_t)1024 * 256,
                                                 w_h + WOFF_INW + 262144, w_l + WOFF_INW + 262144, 1024, 256, 4);
    pack_kernel<<<(256*8*8 + 255) / 256, blk>>>(out_w + (size_t)256 * 512,
                                                w_h + WOFF_OUTW + 131072, w_l + WOFF_OUTW + 131072, 256, 512, 8);

    for (int l = 0; l < NL; l++) {
        if (l > 0) {
            rmsnorm_kernel<<<grid_row, blk>>>(x_p, norm_w + l * 256, xn_p);
            gemm_tc<1><<<grid_proj, gblk, GEMM_SMEM>>>(xn_p, 256,
                                                       w_h + WOFF_INW + l * 262144, w_l + WOFF_INW + l * 262144, 1024,
                                                       h_p, gg_p,
                                                       conv_w + (size_t)l * 512 * 4,
                                                       conv_b + (size_t)l * 512, 1024, 4);
        }
        ssm_kernel<<<grid_ssm, 512, 48 * 512 * sizeof(float)>>>(
            h_p, gg_p,
            xp_w + (size_t)l * 48 * 512,
            dt_w + (size_t)l * 512 * 16,
            dt_b + (size_t)l * 512,
            Dv   + (size_t)l * 512, y_p);
        gemm_tc<2><<<grid_out, gblk, GEMM_SMEM>>>(y_p, 512,
                                                  w_h + WOFF_OUTW + l * 131072, w_l + WOFF_OUTW + l * 131072, 256,
                                                  x_p, nullptr, x_p, nullptr, 256, 8);
    }

    cls_kernel<<<grid_cls, blk>>>(x_p, norm_f_w, cls_w, cls_b, out);
}

// round 13
// speedup vs baseline: 1.0934x; 1.0934x over previous
#include <cuda_runtime.h>
#include <cuda_bf16.h>
#include <math.h>
#include <stdint.h>

#define BATCH 32768
#define B2    (2 * BATCH)
#define NL 2

// ---------------- scratch (device globals; no allocation) ----------------
__device__ float g_x [(size_t)B2 * 256];
__device__ float g_xn[(size_t)B2 * 256];
__device__ float g_h [(size_t)B2 * 512];
__device__ float g_g [(size_t)B2 * 512];
__device__ float g_y [(size_t)B2 * 512];

// packed weights: bf16 hi/lo, layout [S][R][64] rows pre-swizzled (chunk ^= row&7)
__device__ __nv_bfloat16 g_w_hi[1 << 20];
__device__ __nv_bfloat16 g_w_lo[1 << 20];
#define WOFF_MW   0
#define WOFF_RW   131072
#define WOFF_INW  147456
#define WOFF_OUTW (147456 + 2*262144)

__device__ __forceinline__ float silu_f(float x) { return x / (1.0f + __expf(-x)); }
__device__ __forceinline__ float softplus_f(float x) { return (x > 20.0f) ? x : log1pf(__expf(x)); }

__device__ __forceinline__ uint32_t smem_u32_of(const void* p) {
    uint32_t a;
    asm("{ .reg .u64 t; cvta.to.shared.u64 t, %1; cvt.u32.u64 %0, t; }" : "=r"(a) : "l"(p));
    return a;
}
__device__ __forceinline__ uint32_t swzb(uint32_t b) { return b ^ ((b >> 3) & 0x70); }

__device__ __forceinline__ void bsplit2(float x0, float x1, uint32_t& hi, uint32_t& lo) {
    __nv_bfloat16 h0 = __float2bfloat16_rn(x0), h1 = __float2bfloat16_rn(x1);
    float r0 = x0 - __bfloat162float(h0), r1 = x1 - __bfloat162float(h1);
    __nv_bfloat16 l0 = __float2bfloat16_rn(r0), l1 = __float2bfloat16_rn(r1);
    hi = ((uint32_t)__bfloat16_as_ushort(h1) << 16) | __bfloat16_as_ushort(h0);
    lo = ((uint32_t)__bfloat16_as_ushort(l1) << 16) | __bfloat16_as_ushort(l0);
}

#define STS128U(addr, a, b, c, d) \
    asm volatile("st.shared.v4.b32 [%0], {%1, %2, %3, %4};" \
                 :: "r"(addr), "r"(a), "r"(b), "r"(c), "r"(d) : "memory")

#define LDSM4(r0, r1, r2, r3, a) \
    asm volatile("ldmatrix.sync.aligned.m8n8.x4.shared.b16 {%0,%1,%2,%3}, [%4];" \
                 : "=r"(r0), "=r"(r1), "=r"(r2), "=r"(r3) : "r"(a))

__device__ __forceinline__ void mma_bf16(float* c, const uint32_t* a, const uint32_t* b) {
    asm volatile("mma.sync.aligned.m16n8k16.row.col.f32.bf16.bf16.f32 "
                 "{%0,%1,%2,%3}, {%4,%5,%6,%7}, {%8,%9}, {%0,%1,%2,%3};"
                 : "+f"(c[0]), "+f"(c[1]), "+f"(c[2]), "+f"(c[3])
                 : "r"(a[0]), "r"(a[1]), "r"(a[2]), "r"(a[3]), "r"(b[0]), "r"(b[1]));
}

__device__ __forceinline__ void cp16(uint32_t d, const void* s) {
    asm volatile("cp.async.cg.shared.global [%0], [%1], 16;" :: "r"(d), "l"(s) : "memory");
}
#define CP_COMMIT() asm volatile("cp.async.commit_group;" ::: "memory")
#define CP_WAIT0()  asm volatile("cp.async.wait_group 0;" ::: "memory")

// ---------------- pack weights: fp32 [R,K] -> swizzled bf16 hi/lo [S][R][64] ----------------
__global__ __launch_bounds__(256)
void pack_kernel(const float* __restrict__ src, __nv_bfloat16* __restrict__ hi,
                 __nv_bfloat16* __restrict__ lo, int R, int K, int S)
{
    int id = blockIdx.x * 256 + threadIdx.x;
    if (id >= R * S * 8) return;
    int c8  = id & 7;
    int rs  = id >> 3;
    int row = rs % R;
    int s   = rs / R;
    int k0  = s * 64 + c8 * 8;
    const float* sp = src + (size_t)row * K;
    uint32_t h[4], l[4];
    #pragma unroll
    for (int p = 0; p < 4; p++) {
        int k = k0 + p * 2;
        float x0 = (k     < K) ? sp[k]     : 0.0f;
        float x1 = (k + 1 < K) ? sp[k + 1] : 0.0f;
        bsplit2(x0, x1, h[p], l[p]);
    }
    size_t off = ((size_t)s * R + row) * 64 + (size_t)(c8 ^ (row & 7)) * 8;
    *(uint4*)(hi + off) = make_uint4(h[0], h[1], h[2], h[3]);
    *(uint4*)(lo + off) = make_uint4(l[0], l[1], l[2], l[3]);
}

// ---------------- tensor-core GEMM: 512 threads, 16 warps 4(M)x4(N), warp tile 32x32 ----------------
// C[M,N] = A[M,K] @ W[N,K]^T via hh+hl+lh bf16 MMA. CTA 128x128, BK=64, double buffer.
// MODE 0: out0 = acc + e0[n]
// MODE 1: n<512: silu(acc*e0[n*4+3]+e1[n]) -> out0 ; else raw -> out1[m*512+(n-512)]
// MODE 2: out0 = acc + e0[m*N+n]
#define TILE_BYTES  (128 * 128)
#define STAGE_BYTES (4 * TILE_BYTES)
#define GEMM_SMEM   (2 * STAGE_BYTES)       // 128KB

template<int MODE>
__global__ __launch_bounds__(512, 1)
void gemm_tc(const float* __restrict__ A, int K,
             const __nv_bfloat16* __restrict__ Whi, const __nv_bfloat16* __restrict__ Wlo, int RW,
             float* __restrict__ out0, float* __restrict__ out1,
             const float* __restrict__ e0, const float* __restrict__ e1,
             int N, int S)
{
    extern __shared__ char smem[];
    const uint32_t sb = smem_u32_of(smem);

    const int tid  = threadIdx.x;
    const int lane = tid & 31;
    const int wid  = tid >> 5;
    const int bm = blockIdx.y * 128;
    const int bn = blockIdx.x * 128;
    const int wm = (wid >> 2) * 32;     // 0,32,64,96
    const int wn = (wid & 3) * 32;      // 0,32,64,96
    const bool k4 = ((K & 3) == 0);

    float acc[2][4][4];
    #pragma unroll
    for (int i = 0; i < 2; i++)
        #pragma unroll
        for (int j = 0; j < 4; j++)
            #pragma unroll
            for (int c = 0; c < 4; c++) acc[i][j][c] = 0.0f;

    float va[2][8];

    // A: load 128x64 fp32 for stage s into registers (16 elems/thread)
    auto load_regsA = [&](int s) {
        const int k0 = s * 64;
        #pragma unroll
        for (int i = 0; i < 2; i++) {
            int idx = tid + i * 512;
            int m  = idx >> 3;
            int c8 = idx & 7;
            int k  = k0 + c8 * 8;
            const float* ap = A + (size_t)(bm + m) * K;
            if (k4) {
                #pragma unroll
                for (int h = 0; h < 2; h++) {
                    int kk = k + h * 4;
                    float4 u = make_float4(0.f, 0.f, 0.f, 0.f);
                    if (kk + 4 <= K) u = *(const float4*)(ap + kk);
                    va[i][h*4+0] = u.x; va[i][h*4+1] = u.y; va[i][h*4+2] = u.z; va[i][h*4+3] = u.w;
                }
            } else {
                #pragma unroll
                for (int e = 0; e < 8; e++) {
                    int kk = k + e;
                    va[i][e] = (kk < K) ? ap[kk] : 0.0f;
                }
            }
        }
    };
    // A: convert + swizzled STS into stage st
    auto storeA = [&](int st) {
        const uint32_t base = sb + st * STAGE_BYTES;
        #pragma unroll
        for (int i = 0; i < 2; i++) {
            int idx = tid + i * 512;
            int m  = idx >> 3;
            int c8 = idx & 7;
            uint32_t off = swzb((uint32_t)(m * 128 + c8 * 16));
            uint32_t h[4], l[4];
            #pragma unroll
            for (int p = 0; p < 4; p++)
                bsplit2(va[i][2*p], va[i][2*p+1], h[p], l[p]);
            STS128U(base + 0 * TILE_BYTES + off, h[0], h[1], h[2], h[3]);
            STS128U(base + 1 * TILE_BYTES + off, l[0], l[1], l[2], l[3]);
        }
    };
    // W: cp.async hi+lo tiles for stage s into buffer st (4 cp16/thread)
    auto issueW = [&](int s, int st) {
        const uint32_t base = sb + st * STAGE_BYTES;
        #pragma unroll
        for (int t = 0; t < 2; t++) {
            int idx = tid * 2 + t;          // 0..1023
            int row = idx >> 3;
            int u   = idx & 7;
            size_t woff = ((size_t)s * RW + bn + row) * 64;
            uint32_t doff = (uint32_t)(row * 128 + u * 16);
            cp16(base + 2 * TILE_BYTES + doff, (const char*)(Whi + woff) + u * 16);
            cp16(base + 3 * TILE_BYTES + doff, (const char*)(Wlo + woff) + u * 16);
        }
    };

    const int q = lane >> 3;
    const int r = lane & 7;
    auto mma_stage = [&](int st) {
        const uint32_t base = sb + st * STAGE_BYTES;
        const uint32_t Ah = base, Al = base + TILE_BYTES;
        const uint32_t Wh = base + 2 * TILE_BYTES, Wl = base + 3 * TILE_BYTES;
        #pragma unroll
        for (int kb = 0; kb < 4; kb++) {
            uint32_t ah[2][4], al[2][4];
            #pragma unroll
            for (int i = 0; i < 2; i++) {
                uint32_t off = swzb((uint32_t)((wm + 16*i + (q & 1) * 8 + r) * 128
                                               + kb * 32 + (q >> 1) * 16));
                LDSM4(ah[i][0], ah[i][1], ah[i][2], ah[i][3], Ah + off);
                LDSM4(al[i][0], al[i][1], al[i][2], al[i][3], Al + off);
            }
            #pragma unroll
            for (int np = 0; np < 2; np++) {
                uint32_t offb = swzb((uint32_t)((wn + 16*np + (q >> 1) * 8 + r) * 128
                                                + kb * 32 + (q & 1) * 16));
                uint32_t bh[4], bl[4];
                LDSM4(bh[0], bh[1], bh[2], bh[3], Wh + offb);
                LDSM4(bl[0], bl[1], bl[2], bl[3], Wl + offb);
                #pragma unroll
                for (int jj = 0; jj < 2; jj++) {
                    int j = np * 2 + jj;
                    uint32_t Bh[2] = {bh[2*jj], bh[2*jj+1]};
                    uint32_t Bl[2] = {bl[2*jj], bl[2*jj+1]};
                    #pragma unroll
                    for (int i = 0; i < 2; i++) {
                        mma_bf16(acc[i][j], ah[i], Bh);
                        mma_bf16(acc[i][j], ah[i], Bl);
                        mma_bf16(acc[i][j], al[i], Bh);
                    }
                }
            }
        }
    };

    // ---- pipeline ----
    issueW(0, 0); CP_COMMIT();
    load_regsA(0);
    storeA(0);
    CP_WAIT0();
    __syncthreads();

    int st = 0;
    for (int s = 0; s < S; s++) {
        const bool more = (s + 1 < S);
        if (more) {
            issueW(s + 1, st ^ 1); CP_COMMIT();
            load_regsA(s + 1);
        }
        mma_stage(st);
        if (more) {
            storeA(st ^ 1);
            CP_WAIT0();
            __syncthreads();
            st ^= 1;
        }
    }

    // ---- epilogue ----
    #pragma unroll
    for (int i = 0; i < 2; i++) {
        int r0 = bm + wm + 16 * i + (lane >> 2);
        #pragma unroll
        for (int j = 0; j < 4; j++) {
            int c = bn + wn + 8 * j + (lane & 3) * 2;
            #pragma unroll
            for (int hrow = 0; hrow < 2; hrow++) {
                int m = r0 + hrow * 8;
                float v0 = acc[i][j][hrow * 2 + 0];
                float v1 = acc[i][j][hrow * 2 + 1];
                if (MODE == 0) {
                    *(float2*)(out0 + (size_t)m * N + c) = make_float2(v0 + e0[c], v1 + e0[c + 1]);
                } else if (MODE == 1) {
                    if (c < 512) {
                        float2 o;
                        o.x = silu_f(fmaf(v0, e0[c * 4 + 3], e1[c]));
                        o.y = silu_f(fmaf(v1, e0[(c + 1) * 4 + 3], e1[c + 1]));
                        *(float2*)(out0 + (size_t)m * 512 + c) = o;
                    } else {
                        *(float2*)(out1 + (size_t)m * 512 + (c - 512)) = make_float2(v0, v1);
                    }
                } else {
                    float2 rr = *(const float2*)(e0 + (size_t)m * N + c);
                    *(float2*)(out0 + (size_t)m * N + c) = make_float2(v0 + rr.x, v1 + rr.y);
                }
            }
        }
    }
}

// ---------------- fused SSM with smem-staged xp_w ----------------
__global__ __launch_bounds__(512)
void ssm_kernel(const float* __restrict__ h, const float* __restrict__ gate,
                const float* __restrict__ xp_w, const float* __restrict__ dt_w,
                const float* __restrict__ dt_b, const float* __restrict__ Dv,
                float* __restrict__ y)
{
    extern __shared__ float s_xp[];
    #pragma unroll 4
    for (int i = threadIdx.x; i < 48 * 512; i += 512) s_xp[i] = xp_w[i];
    __syncthreads();

    const int warp = threadIdx.x >> 5;
    const int lane = threadIdx.x & 31;
    const size_t row = (size_t)blockIdx.x * 16 + warp;

    const float* hr = h + row * 512;
    float hreg[16];
    #pragma unroll
    for (int qq = 0; qq < 16; qq++) hreg[qq] = hr[lane + 32 * qq];

    float dtv[16], bnv[16];
    float bc = 0.0f;
    #pragma unroll
    for (int j = 0; j < 48; j++) {
        const float* w = s_xp + j * 512;
        float p = 0.0f;
        #pragma unroll
        for (int qq = 0; qq < 16; qq++) p = fmaf(hreg[qq], w[lane + 32 * qq], p);
        #pragma unroll
        for (int o = 16; o > 0; o >>= 1) p += __shfl_xor_sync(0xffffffffu, p, o);
        if (j < 16)       dtv[j] = p;
        else if (j < 32)  bnv[j - 16] = p;
        else              bc = fmaf(bnv[j - 32], p, bc);
    }

    #pragma unroll
    for (int qq = 0; qq < 16; qq++) {
        int i = lane + 32 * qq;
        const float4* wr = (const float4*)(dt_w + (size_t)i * 16);
        float t = dt_b[i];
        #pragma unroll
        for (int c = 0; c < 4; c++) {
            float4 w4 = wr[c];
            t = fmaf(dtv[c * 4 + 0], w4.x, t);
            t = fmaf(dtv[c * 4 + 1], w4.y, t);
            t = fmaf(dtv[c * 4 + 2], w4.z, t);
            t = fmaf(dtv[c * 4 + 3], w4.w, t);
        }
        float sp = softplus_f(t);
        float gv = gate[row * 512 + i];
        y[row * 512 + i] = hreg[qq] * fmaf(sp, bc, Dv[i]) * silu_f(gv);
    }
}

// ---------------- rmsnorm (per-layer) ----------------
__global__ __launch_bounds__(256)
void rmsnorm_kernel(const float* __restrict__ x, const float* __restrict__ w,
                    float* __restrict__ out)
{
    const int warp = threadIdx.x >> 5;
    const int lane = threadIdx.x & 31;
    const size_t row = (size_t)blockIdx.x * 8 + warp;

    float v[8];
    float ss = 0.0f;
    #pragma unroll
    for (int qq = 0; qq < 8; qq++) {
        v[qq] = x[row * 256 + lane + 32 * qq];
        ss = fmaf(v[qq], v[qq], ss);
    }
    #pragma unroll
    for (int o = 16; o > 0; o >>= 1) ss += __shfl_xor_sync(0xffffffffu, ss, o);
    float inv = rsqrtf(ss * (1.0f / 256.0f) + 1e-5f);
    #pragma unroll
    for (int qq = 0; qq < 8; qq++)
        out[row * 256 + lane + 32 * qq] = v[qq] * inv * w[lane + 32 * qq];
}

// ---------------- classifier with fused final rmsnorm ----------------
__global__ __launch_bounds__(256)
void cls_kernel(const float* __restrict__ x, const float* __restrict__ wf,
                const float* __restrict__ cw, const float* __restrict__ cb,
                float* __restrict__ out)
{
    const int warp = threadIdx.x >> 5;
    const int lane = threadIdx.x & 31;
    const size_t row = (size_t)blockIdx.x * 8 + warp;

    float va[8], vb[8];
    float sa = 0.0f, sb2 = 0.0f;
    #pragma unroll
    for (int qq = 0; qq < 8; qq++) {
        size_t ia = row * 256 + lane + 32 * qq;
        size_t ib = ((size_t)BATCH + row) * 256 + lane + 32 * qq;
        va[qq] = x[ia]; vb[qq] = x[ib];
        sa  = fmaf(va[qq], va[qq], sa);
        sb2 = fmaf(vb[qq], vb[qq], sb2);
    }
    #pragma unroll
    for (int o = 16; o > 0; o >>= 1) {
        sa  += __shfl_xor_sync(0xffffffffu, sa,  o);
        sb2 += __shfl_xor_sync(0xffffffffu, sb2, o);
    }
    float inva = rsqrtf(sa  * (1.0f / 256.0f) + 1e-5f);
    float invb = rsqrtf(sb2 * (1.0f / 256.0f) + 1e-5f);

    float p[8];
    #pragma unroll
    for (int qq = 0; qq < 8; qq++) {
        float w = wf[lane + 32 * qq];
        p[qq] = 0.5f * (va[qq] * inva + vb[qq] * invb) * w;
    }
    #pragma unroll
    for (int j = 0; j < 5; j++) {
        float s = 0.0f;
        #pragma unroll
        for (int qq = 0; qq < 8; qq++) s = fmaf(p[qq], cw[j * 256 + lane + 32 * qq], s);
        #pragma unroll
        for (int o = 16; o > 0; o >>= 1) s += __shfl_xor_sync(0xffffffffu, s, o);
        if (lane == 0) out[row * 5 + j] = s + cb[j];
    }
}

// ---------------- launch ----------------
extern "C" void kernel_launch(void* const* d_in, const int* in_sizes, int n_in,
                              void* d_out, int out_size)
{
    const float* methyl   = (const float*)d_in[0];
    const float* rna      = (const float*)d_in[1];
    const float* methyl_w = (const float*)d_in[2];
    const float* methyl_b = (const float*)d_in[3];
    const float* rna_w    = (const float*)d_in[4];
    const float* rna_b    = (const float*)d_in[5];
    const float* in_w     = (const float*)d_in[6];
    const float* conv_w   = (const float*)d_in[7];
    const float* conv_b   = (const float*)d_in[8];
    const float* xp_w     = (const float*)d_in[9];
    const float* dt_w     = (const float*)d_in[10];
    const float* dt_b     = (const float*)d_in[11];
    const float* Dv       = (const float*)d_in[13];
    const float* out_w    = (const float*)d_in[14];
    const float* norm_w   = (const float*)d_in[15];
    const float* norm_f_w = (const float*)d_in[16];
    const float* cls_w    = (const float*)d_in[17];
    const float* cls_b    = (const float*)d_in[18];
    float* out = (float*)d_out;

    float* x_p;  cudaGetSymbolAddress((void**)&x_p,  g_x);
    float* xn_p; cudaGetSymbolAddress((void**)&xn_p, g_xn);
    float* h_p;  cudaGetSymbolAddress((void**)&h_p,  g_h);
    float* gg_p; cudaGetSymbolAddress((void**)&gg_p, g_g);
    float* y_p;  cudaGetSymbolAddress((void**)&y_p,  g_y);
    __nv_bfloat16 *w_h, *w_l;
    cudaGetSymbolAddress((void**)&w_h, g_w_hi);
    cudaGetSymbolAddress((void**)&w_l, g_w_lo);

    cudaFuncSetAttribute(ssm_kernel, cudaFuncAttributeMaxDynamicSharedMemorySize, 48 * 512 * sizeof(float));
    cudaFuncSetAttribute(gemm_tc<0>, cudaFuncAttributeMaxDynamicSharedMemorySize, GEMM_SMEM);
    cudaFuncSetAttribute(gemm_tc<1>, cudaFuncAttributeMaxDynamicSharedMemorySize, GEMM_SMEM);
    cudaFuncSetAttribute(gemm_tc<2>, cudaFuncAttributeMaxDynamicSharedMemorySize, GEMM_SMEM);

    dim3 blk(256);
    dim3 gblk(512);

    // ---- pack weights only ----
    auto packs = [&](const float* src, int woff, int R, int K, int S) {
        int total = R * S * 8;
        pack_kernel<<<(total + 255) / 256, blk>>>(src, w_h + woff, w_l + woff, R, K, S);
    };
    packs(methyl_w, WOFF_MW, 256, 500, 8);
    packs(rna_w,    WOFF_RW, 256, 47, 1);
    for (int l = 0; l < NL; l++) {
        packs(in_w  + (size_t)l * 1024 * 256, WOFF_INW  + l * 262144, 1024, 256, 4);
        packs(out_w + (size_t)l * 256 * 512,  WOFF_OUTW + l * 131072, 256, 512, 8);
    }

    // ---- embeddings ----
    dim3 grid_emb(2, BATCH / 128);
    gemm_tc<0><<<grid_emb, gblk, GEMM_SMEM>>>(methyl, 500, w_h + WOFF_MW, w_l + WOFF_MW, 256,
                                              x_p, nullptr, methyl_b, nullptr, 256, 8);
    gemm_tc<0><<<grid_emb, gblk, GEMM_SMEM>>>(rna, 47, w_h + WOFF_RW, w_l + WOFF_RW, 256,
                                              x_p + (size_t)BATCH * 256, nullptr, rna_b, nullptr, 256, 1);

    dim3 grid_proj(8, B2 / 128);
    dim3 grid_out(2, B2 / 128);
    dim3 grid_row(B2 / 8);
    dim3 grid_ssm(B2 / 16);
    dim3 grid_cls(BATCH / 8);

    for (int l = 0; l < NL; l++) {
        rmsnorm_kernel<<<grid_row, blk>>>(x_p, norm_w + l * 256, xn_p);
        gemm_tc<1><<<grid_proj, gblk, GEMM_SMEM>>>(xn_p, 256,
                                                   w_h + WOFF_INW + l * 262144, w_l + WOFF_INW + l * 262144, 1024,
                                                   h_p, gg_p,
                                                   conv_w + (size_t)l * 512 * 4,
                                                   conv_b + (size_t)l * 512, 1024, 4);
        ssm_kernel<<<grid_ssm, 512, 48 * 512 * sizeof(float)>>>(
            h_p, gg_p,
            xp_w + (size_t)l * 48 * 512,
            dt_w + (size_t)l * 512 * 16,
            dt_b + (size_t)l * 512,
            Dv   + (size_t)l * 512, y_p);
        gemm_tc<2><<<grid_out, gblk, GEMM_SMEM>>>(y_p, 512,
                                                  w_h + WOFF_OUTW + l * 131072, w_l + WOFF_OUTW + l * 131072, 256,
                                                  x_p, nullptr, x_p, nullptr, 256, 8);
    }

    cls_kernel<<<grid_cls, blk>>>(x_p, norm_f_w, cls_w, cls_b, out);
}